// round 10
// baseline (speedup 1.0000x reference)
#include <cuda_runtime.h>
#include <cuda_bf16.h>
#include <math.h>

#define Bsz 4
#define Cch 192
#define Hh 56
#define Ww 56
#define HW (Hh*Ww)

// scratch (static device globals; no allocation)
__device__ float g_xt  [Bsz*HW*Cch];  // x transposed to [b][n][c]  (NHWC)
__device__ float g_att [Bsz*HW*Cch];  // attention output, h-shift part
__device__ float g_attw[Bsz*HW*Cch];  // attention output, w-shift part
__device__ float g_sc  [Bsz*HW*32];   // scores, padded row of 32
__device__ __align__(16) __nv_bfloat16 g_wh[Cch*2*Cch];  // weights hi bf16 [o][k]
__device__ __align__(16) __nv_bfloat16 g_wl[Cch*2*Cch];  // weights lo bf16 [o][k]
__device__ float g_scale[Cch];        // BN fused scale
__device__ float g_shift[Cch];        // BN fused shift (incl conv bias)

// pack two fp32 into bf16x2: d.lo = LO, d.hi = HI
#define CVT2(r, LO, HI) \
    asm("cvt.rn.bf16x2.f32 %0, %1, %2;" : "=r"(r) : "f"(HI), "f"(LO))

__device__ __forceinline__ void mma16816(float* c, const unsigned* a,
                                         const unsigned* b)
{
    asm volatile(
        "mma.sync.aligned.m16n8k16.row.col.f32.bf16.bf16.f32 "
        "{%0,%1,%2,%3}, {%4,%5,%6,%7}, {%8,%9}, {%0,%1,%2,%3};"
        : "+f"(c[0]), "+f"(c[1]), "+f"(c[2]), "+f"(c[3])
        : "r"(a[0]), "r"(a[1]), "r"(a[2]), "r"(a[3]), "r"(b[0]), "r"(b[1]));
}

// ---------------------------------------------------------------------------
// Kernel 0: weight fp32 -> bf16 hi/lo split + fused BN params
// ---------------------------------------------------------------------------
__global__ __launch_bounds__(256) void wconv_k(
    const float* __restrict__ cw, const float* __restrict__ bias,
    const float* __restrict__ gamma, const float* __restrict__ beta,
    const float* __restrict__ mean, const float* __restrict__ var)
{
    int i = blockIdx.x*256 + threadIdx.x;        // 18432 threads x 4 elems
    float4 v = *reinterpret_cast<const float4*>(&cw[i*4]);
    float vv[4] = {v.x, v.y, v.z, v.w};
    unsigned hp[2], lp[2];
#pragma unroll
    for (int j = 0; j < 2; j++) {
        unsigned h; CVT2(h, vv[2*j], vv[2*j+1]);
        float f0 = __uint_as_float(h << 16);
        float f1 = __uint_as_float(h & 0xffff0000u);
        unsigned l; CVT2(l, vv[2*j] - f0, vv[2*j+1] - f1);
        hp[j] = h; lp[j] = l;
    }
    *reinterpret_cast<uint2*>(&g_wh[i*4]) = make_uint2(hp[0], hp[1]);
    *reinterpret_cast<uint2*>(&g_wl[i*4]) = make_uint2(lp[0], lp[1]);
    if (i < Cch) {
        float inv = gamma[i] * rsqrtf(var[i] + 1e-5f);
        g_scale[i] = inv;
        g_shift[i] = beta[i] + (bias[i] - mean[i]) * inv;
    }
}

// ---------------------------------------------------------------------------
// Kernel 1: NCHW -> NHWC transpose
// ---------------------------------------------------------------------------
__global__ __launch_bounds__(256) void transpose_k(const float* __restrict__ x)
{
    __shared__ float tile[32][33];
    const int n0 = blockIdx.x << 5;
    const int c0 = blockIdx.y << 5;
    const int b  = blockIdx.z;
    const int tx = threadIdx.x, ty = threadIdx.y;
    const float* xb = x + (size_t)b * Cch * HW;
#pragma unroll
    for (int i = 0; i < 4; i++)
        tile[ty + i*8][tx] = xb[(size_t)(c0 + ty + i*8) * HW + n0 + tx];
    __syncthreads();
    float* dst = g_xt + (size_t)b * HW * Cch;
#pragma unroll
    for (int i = 0; i < 4; i++)
        dst[(size_t)(n0 + ty + i*8) * Cch + c0 + tx] = tile[tx][ty + i*8];
}

// ---------------------------------------------------------------------------
// tanh: (1-e)/(1+e) = 2*rcp(1+e) - 1,  e = 2^(-2a*log2e).  6 instr / 2 MUFU.
// ---------------------------------------------------------------------------
__device__ __forceinline__ float fast_tanh(float p)
{
    float z = fabsf(p) * -2.885390082f;
    float e; asm("ex2.approx.f32 %0, %1;" : "=f"(e) : "f"(z));
    float d = 1.0f + e;
    float r; asm("rcp.approx.f32 %0, %1;" : "=f"(r) : "f"(d));
    float t = fmaf(2.0f, r, -1.0f);
    return copysignf(t, p);
}

// ---------------------------------------------------------------------------
// Kernel 2: ring pair-score kernel (unchanged)
// ---------------------------------------------------------------------------
#define TS_STRIDE 193

template<int LO, int HI, int MODE>
__device__ __forceinline__ void score_compute(const float* sxr, const float* xr,
                                              float* ts, int c)
{
    int p = 0;
#pragma unroll
    for (int i = 0; i < 14; i++)
#pragma unroll
        for (int j = (MODE ? i + 1 : i); j < 14; j++) {
            if (p >= LO && p < HI)
                ts[(p - LO)*TS_STRIDE + c] = fast_tanh(sxr[i] * xr[j]);
            p++;
        }
}

__device__ __forceinline__ void reduce_rows(const float* ts, float* redS,
                                            int c, int nrows, int base)
{
    if (c < nrows) {
        const float* row = ts + c*TS_STRIDE;
        float s0=0.f, s1=0.f, s2=0.f, s3=0.f;
#pragma unroll 8
        for (int cc = 0; cc < 192; cc += 4) {
            s0 += row[cc]; s1 += row[cc+1]; s2 += row[cc+2]; s3 += row[cc+3];
        }
        redS[base + c] = (s0 + s1) + (s2 + s3);
    }
}

__global__ __launch_bounds__(192) void score_k()
{
    __shared__ float ts[53 * TS_STRIDE];
    __shared__ float redS[105];
    const int x = blockIdx.x;
    const int r = blockIdx.y;
    const int b = blockIdx.z >> 1, mode = blockIdx.z & 1;
    const int c = threadIdx.x;
    const float* base = g_xt + (size_t)b * HW * Cch;

    float xr[14], sxr[14];
#pragma unroll
    for (int a = 0; a < 14; a++) {
        int n = mode ? (x*Ww + r + 4*a) : ((r + 4*a)*Ww + x);
        xr[a]  = base[n*Cch + c];
        sxr[a] = xr[a] * 0.19245008972987526f;
    }
    const int NP = mode ? 91 : 105;

    if (mode == 0) score_compute<0,53,0>(sxr, xr, ts, c);
    else           score_compute<0,53,1>(sxr, xr, ts, c);
    __syncthreads();
    reduce_rows(ts, redS, c, 53, 0);
    __syncthreads();
    if (mode == 0) score_compute<53,105,0>(sxr, xr, ts, c);
    else           score_compute<53,91,1>(sxr, xr, ts, c);
    __syncthreads();
    reduce_rows(ts, redS, c, NP - 53, 53);
    __syncthreads();

    float* scb = g_sc + (size_t)b * HW * 32;
    if (mode == 0) {
        for (int e = c; e < 196; e += 192) {
            int a = e / 14, k = e % 14;
            int j = a - k; if (j < 0) j += 14;
            int lo = min(a, j), hi = max(a, j);
            int id = lo*14 - (lo*(lo-1))/2 + (hi - lo);
            int n = (r + 4*a)*Ww + x;
            scb[n*32 + k] = redS[id];
        }
    } else {
        for (int e = c; e < 182; e += 192) {
            int a = e / 13, m = e % 13 + 1;
            int j = a - m; if (j < 0) j += 14;
            int lo = min(a, j), hi = max(a, j);
            int id = lo*13 - (lo*(lo-1))/2 + (hi - lo - 1);
            int n = x*Ww + r + 4*a;
            scb[n*32 + 13 + m] = redS[id];
        }
    }
}

// ---------------------------------------------------------------------------
// Kernel 3: ring weighted-sum (unchanged)
// ---------------------------------------------------------------------------
__global__ __launch_bounds__(192) void sum_k()
{
    __shared__ float wgt[14*14];
    const int x = blockIdx.x, r = blockIdx.y;
    const int b = blockIdx.z >> 1, mode = blockIdx.z & 1;
    const int c = threadIdx.x;
    const float* base = g_xt + (size_t)b * HW * Cch;
    float* attb = (mode ? g_attw : g_att) + (size_t)b * HW * Cch;
    const float* scb = g_sc + (size_t)b * HW * 32;

    if (c < 14) {
        int n = mode ? (x*Ww + r + 4*c) : ((r + 4*c)*Ww + x);
        const float* srow = scb + n*32;
        float s[27], mx = -1e30f;
#pragma unroll
        for (int k = 0; k < 27; k++) { s[k] = srow[k]; mx = fmaxf(mx, s[k]); }
        float tot = 0.f;
#pragma unroll
        for (int k = 0; k < 27; k++) { s[k] = __expf(s[k] - mx); tot += s[k]; }
        float inv = __fdividef(1.f, tot);
        if (mode == 0) {
#pragma unroll
            for (int k = 0; k < 14; k++) wgt[c*14 + k] = s[k] * inv;
        } else {
#pragma unroll
            for (int m = 1; m < 14; m++) wgt[c*14 + m-1] = s[13 + m] * inv;
        }
    }
    __syncthreads();

    float xr[14];
#pragma unroll
    for (int a = 0; a < 14; a++) {
        int n = mode ? (x*Ww + r + 4*a) : ((r + 4*a)*Ww + x);
        xr[a] = base[n*Cch + c];
    }
#pragma unroll
    for (int a = 0; a < 14; a++) {
        int n = mode ? (x*Ww + r + 4*a) : ((r + 4*a)*Ww + x);
        float o = 0.f;
        if (mode == 0) {
#pragma unroll
            for (int k = 0; k < 14; k++) {
                int j = (a - k + 14) % 14;
                o = fmaf(wgt[a*14 + k], xr[j], o);
            }
        } else {
#pragma unroll
            for (int m = 1; m < 14; m++) {
                int j = (a - m + 14) % 14;
                o = fmaf(wgt[a*14 + m-1], xr[j], o);
            }
        }
        attb[n*Cch + c] = o;
    }
}

// ---------------------------------------------------------------------------
// Kernel 4: tensor-core GEMM via mma.sync m16n8k16 bf16x3 (fp32-accurate).
// Block 128 rows x 64 channels, grid 98x3 = 294 = 148 SMs x 2 (even waves).
// B staged in dynamic smem per 64-k chunk (stride-36-word rows: fragment
// LDS.32 banks 4g+tt conflict-free). NO global loads in the MMA loop.
// A and B both register-prefetched during previous chunk's MMAs.
// ---------------------------------------------------------------------------
#define AStr 72   // bf16 per A row (36 words)
#define BStr 36   // words per B row (32 k-pairs + 4 pad)
#define A_BYTES (128*AStr*2)          // 18432 per half
#define B_BYTES (64*BStr*4)           // 9216 per half
#define DSMB (2*A_BYTES + 2*B_BYTES)  // 55296

__global__ __launch_bounds__(256, 2) void gemm_mma(float* __restrict__ out)
{
    extern __shared__ __align__(16) char dsm[];
    __nv_bfloat16* Ah = reinterpret_cast<__nv_bfloat16*>(dsm);
    __nv_bfloat16* Al = Ah + 128*AStr;
    unsigned* Bh = reinterpret_cast<unsigned*>(dsm + 2*A_BYTES);
    unsigned* Bl = Bh + 64*BStr;

    const int t = threadIdx.x, lane = t & 31, wid = t >> 5;
    const int g = lane >> 2, tt = lane & 3;
    const int rwarp = (wid & 3) * 32;        // 4 row-warps
    const int cwarp = (wid >> 2) * 32;       // 2 ch-warps of 32
    const int r0 = blockIdx.x * 128;         // global row (batch folded)
    const int o0 = blockIdx.y * 64;          // channel third

    float acc[2][4][4];
#pragma unroll
    for (int rt = 0; rt < 2; rt++)
#pragma unroll
        for (int ct = 0; ct < 4; ct++)
#pragma unroll
            for (int q = 0; q < 4; q++) acc[rt][ct][q] = 0.f;

    // B loader coords: 4 threads per o row, each covers 2x16B per half
    const int bo = t >> 2, bq = (t & 3) * 8;        // bf16 offset in 64-k row

    float4 pv[8];
    uint4 bvh[2], bvl[2];
#define LOAD_CHUNK(I) do {                                                    \
        const int kc_ = ((I) < 3) ? (I)*64 : ((I) - 3)*64;                    \
        const int kw_ = (I)*64;                                               \
        _Pragma("unroll")                                                     \
        for (int s = 0; s < 8; s++) {                                         \
            int f = t + 256*s, row = f >> 4, kq = (f & 15) * 4;               \
            size_t gix = (size_t)(r0 + row)*Cch + kc_ + kq;                   \
            if ((I) < 3) pv[s] = *reinterpret_cast<const float4*>(&g_xt[gix]);\
            else {                                                            \
                float4 h = *reinterpret_cast<const float4*>(&g_att[gix]);     \
                float4 w = *reinterpret_cast<const float4*>(&g_attw[gix]);    \
                pv[s] = make_float4(h.x+w.x, h.y+w.y, h.z+w.z, h.w+w.w);      \
            }                                                                 \
        }                                                                     \
        const __nv_bfloat16* wph = &g_wh[(o0 + bo)*384 + kw_ + bq];           \
        const __nv_bfloat16* wpl = &g_wl[(o0 + bo)*384 + kw_ + bq];           \
        bvh[0] = *reinterpret_cast<const uint4*>(wph);                        \
        bvh[1] = *reinterpret_cast<const uint4*>(wph + 32);                   \
        bvl[0] = *reinterpret_cast<const uint4*>(wpl);                        \
        bvl[1] = *reinterpret_cast<const uint4*>(wpl + 32);                   \
    } while (0)

    LOAD_CHUNK(0);
#pragma unroll 1
    for (int i = 0; i < 6; i++) {
        __syncthreads();
        // A: convert + store hi/lo into padded smem
#pragma unroll
        for (int s = 0; s < 8; s++) {
            int f = t + 256*s, row = f >> 4, kq = (f & 15) * 4;
            float v0 = pv[s].x, v1 = pv[s].y, v2 = pv[s].z, v3 = pv[s].w;
            unsigned h0, h1, l0, l1;
            CVT2(h0, v0, v1);
            CVT2(h1, v2, v3);
            CVT2(l0, v0 - __uint_as_float(h0 << 16),
                     v1 - __uint_as_float(h0 & 0xffff0000u));
            CVT2(l1, v2 - __uint_as_float(h1 << 16),
                     v3 - __uint_as_float(h1 & 0xffff0000u));
            *reinterpret_cast<uint2*>(&Ah[row*AStr + kq]) = make_uint2(h0, h1);
            *reinterpret_cast<uint2*>(&Al[row*AStr + kq]) = make_uint2(l0, l1);
        }
        // B: scatter 4-word groups (pair index = bq/2, second 16B at +16 pairs)
        {
            const int wb = bo*BStr + (bq >> 1);
            const unsigned* ph0 = &bvh[0].x;
            const unsigned* ph1 = &bvh[1].x;
            const unsigned* pl0 = &bvl[0].x;
            const unsigned* pl1 = &bvl[1].x;
#pragma unroll
            for (int j = 0; j < 4; j++) {
                Bh[wb + j]      = ph0[j];
                Bh[wb + 16 + j] = ph1[j];
                Bl[wb + j]      = pl0[j];
                Bl[wb + 16 + j] = pl1[j];
            }
        }
        __syncthreads();
        if (i < 5) LOAD_CHUNK(i + 1);

#pragma unroll
        for (int kk = 0; kk < 4; kk++) {
            unsigned bh[4][2], bl[4][2];
#pragma unroll
            for (int ct = 0; ct < 4; ct++) {
                const int wbase = (cwarp + ct*8 + g)*BStr + kk*8 + tt;
                bh[ct][0] = Bh[wbase];  bh[ct][1] = Bh[wbase + 4];
                bl[ct][0] = Bl[wbase];  bl[ct][1] = Bl[wbase + 4];
            }
#pragma unroll
            for (int rt = 0; rt < 2; rt++) {
                const int rb = rwarp + rt*16 + g;
                const int cb = kk*16 + 2*tt;
                unsigned ah[4], al[4];
                ah[0] = *reinterpret_cast<const unsigned*>(&Ah[rb*AStr + cb]);
                ah[1] = *reinterpret_cast<const unsigned*>(&Ah[(rb+8)*AStr + cb]);
                ah[2] = *reinterpret_cast<const unsigned*>(&Ah[rb*AStr + cb + 8]);
                ah[3] = *reinterpret_cast<const unsigned*>(&Ah[(rb+8)*AStr + cb + 8]);
                al[0] = *reinterpret_cast<const unsigned*>(&Al[rb*AStr + cb]);
                al[1] = *reinterpret_cast<const unsigned*>(&Al[(rb+8)*AStr + cb]);
                al[2] = *reinterpret_cast<const unsigned*>(&Al[rb*AStr + cb + 8]);
                al[3] = *reinterpret_cast<const unsigned*>(&Al[(rb+8)*AStr + cb + 8]);
#pragma unroll
                for (int ct = 0; ct < 4; ct++) {
                    mma16816(acc[rt][ct], ah, bh[ct]);
                    mma16816(acc[rt][ct], ah, bl[ct]);
                    mma16816(acc[rt][ct], al, bh[ct]);
                }
            }
        }
    }

    // epilogue: BN scale/shift + exact GELU, scattered STG.32
#pragma unroll
    for (int rt = 0; rt < 2; rt++) {
        const int rr = r0 + rwarp + rt*16 + g;
        const int b0_ = rr / HW,       n0_ = rr - b0_*HW;
        const int b1_ = (rr + 8) / HW, n1_ = (rr + 8) - b1_*HW;
#pragma unroll
        for (int ct = 0; ct < 4; ct++) {
            const int o = o0 + cwarp + ct*8 + 2*tt;
            const float sc0 = __ldg(&g_scale[o]),   sh0 = __ldg(&g_shift[o]);
            const float sc1 = __ldg(&g_scale[o+1]), sh1 = __ldg(&g_shift[o+1]);
            float y0 = fmaf(acc[rt][ct][0], sc0, sh0);
            float y1 = fmaf(acc[rt][ct][1], sc1, sh1);
            float y2 = fmaf(acc[rt][ct][2], sc0, sh0);
            float y3 = fmaf(acc[rt][ct][3], sc1, sh1);
            size_t i00 = (size_t)(b0_*Cch + o)*HW + n0_;
            size_t i10 = (size_t)(b1_*Cch + o)*HW + n1_;
            out[i00]      = 0.5f*y0*(1.0f + erff(y0*0.70710678118654752f));
            out[i00 + HW] = 0.5f*y1*(1.0f + erff(y1*0.70710678118654752f));
            out[i10]      = 0.5f*y2*(1.0f + erff(y2*0.70710678118654752f));
            out[i10 + HW] = 0.5f*y3*(1.0f + erff(y3*0.70710678118654752f));
        }
    }
}

// ---------------------------------------------------------------------------
extern "C" void kernel_launch(void* const* d_in, const int* in_sizes, int n_in,
                              void* d_out, int out_size)
{
    const float* x     = (const float*)d_in[0];
    const float* cw    = (const float*)d_in[1];
    const float* cb    = (const float*)d_in[2];
    const float* gamma = (const float*)d_in[3];
    const float* beta  = (const float*)d_in[4];
    const float* mean  = (const float*)d_in[5];
    const float* var   = (const float*)d_in[6];
    float* out = (float*)d_out;

    cudaFuncSetAttribute(gemm_mma, cudaFuncAttributeMaxDynamicSharedMemorySize,
                         DSMB);
    wconv_k<<<72, 256>>>(cw, cb, gamma, beta, mean, var);
    transpose_k<<<dim3(HW/32, Cch/32, Bsz), dim3(32, 8)>>>(x);
    score_k<<<dim3(56, 4, 2*Bsz), 192>>>();
    sum_k<<<dim3(56, 4, 2*Bsz), 192>>>();
    gemm_mma<<<dim3(98, 3), 256, DSMB>>>(out);
}

// round 11
// speedup vs baseline: 1.1893x; 1.1893x over previous
#include <cuda_runtime.h>
#include <math.h>

#define Bsz 4
#define Cch 192
#define Hh 56
#define Ww 56
#define HW (Hh*Ww)

// scratch (static device globals; no allocation)
__device__ float g_xt  [Bsz*HW*Cch];  // x transposed to [b][n][c]  (NHWC)
__device__ float g_att [Bsz*HW*Cch];  // attention output, h-shift part
__device__ float g_attw[Bsz*HW*Cch];  // attention output, w-shift part
__device__ float g_sc  [Bsz*HW*32];   // scores, padded row of 32

// ---------------------------------------------------------------------------
// Kernel 1: NCHW -> NHWC transpose
// ---------------------------------------------------------------------------
__global__ __launch_bounds__(256) void transpose_k(const float* __restrict__ x)
{
    __shared__ float tile[32][33];
    const int n0 = blockIdx.x << 5;
    const int c0 = blockIdx.y << 5;
    const int b  = blockIdx.z;
    const int tx = threadIdx.x, ty = threadIdx.y;
    const float* xb = x + (size_t)b * Cch * HW;
#pragma unroll
    for (int i = 0; i < 4; i++)
        tile[ty + i*8][tx] = xb[(size_t)(c0 + ty + i*8) * HW + n0 + tx];
    __syncthreads();
    float* dst = g_xt + (size_t)b * HW * Cch;
#pragma unroll
    for (int i = 0; i < 4; i++)
        dst[(size_t)(n0 + ty + i*8) * Cch + c0 + tx] = tile[tx][ty + i*8];
}

// ---------------------------------------------------------------------------
// tanh: (1-e)/(1+e) = 2*rcp(1+e) - 1,  e = 2^(-2a*log2e).  6 instr / 2 MUFU.
// ---------------------------------------------------------------------------
__device__ __forceinline__ float fast_tanh(float p)
{
    float z = fabsf(p) * -2.885390082f;
    float e; asm("ex2.approx.f32 %0, %1;" : "=f"(e) : "f"(z));
    float d = 1.0f + e;
    float r; asm("rcp.approx.f32 %0, %1;" : "=f"(r) : "f"(d));
    float t = fmaf(2.0f, r, -1.0f);
    return copysignf(t, p);
}

// ---------------------------------------------------------------------------
// Kernel 2: ring pair-score kernel (unchanged)
// ---------------------------------------------------------------------------
#define TS_STRIDE 193

template<int LO, int HI, int MODE>
__device__ __forceinline__ void score_compute(const float* sxr, const float* xr,
                                              float* ts, int c)
{
    int p = 0;
#pragma unroll
    for (int i = 0; i < 14; i++)
#pragma unroll
        for (int j = (MODE ? i + 1 : i); j < 14; j++) {
            if (p >= LO && p < HI)
                ts[(p - LO)*TS_STRIDE + c] = fast_tanh(sxr[i] * xr[j]);
            p++;
        }
}

__device__ __forceinline__ void reduce_rows(const float* ts, float* redS,
                                            int c, int nrows, int base)
{
    if (c < nrows) {
        const float* row = ts + c*TS_STRIDE;
        float s0=0.f, s1=0.f, s2=0.f, s3=0.f;
#pragma unroll 8
        for (int cc = 0; cc < 192; cc += 4) {
            s0 += row[cc]; s1 += row[cc+1]; s2 += row[cc+2]; s3 += row[cc+3];
        }
        redS[base + c] = (s0 + s1) + (s2 + s3);
    }
}

__global__ __launch_bounds__(192) void score_k()
{
    __shared__ float ts[53 * TS_STRIDE];
    __shared__ float redS[105];
    const int x = blockIdx.x;
    const int r = blockIdx.y;
    const int b = blockIdx.z >> 1, mode = blockIdx.z & 1;
    const int c = threadIdx.x;
    const float* base = g_xt + (size_t)b * HW * Cch;

    float xr[14], sxr[14];
#pragma unroll
    for (int a = 0; a < 14; a++) {
        int n = mode ? (x*Ww + r + 4*a) : ((r + 4*a)*Ww + x);
        xr[a]  = base[n*Cch + c];
        sxr[a] = xr[a] * 0.19245008972987526f;
    }
    const int NP = mode ? 91 : 105;

    if (mode == 0) score_compute<0,53,0>(sxr, xr, ts, c);
    else           score_compute<0,53,1>(sxr, xr, ts, c);
    __syncthreads();
    reduce_rows(ts, redS, c, 53, 0);
    __syncthreads();
    if (mode == 0) score_compute<53,105,0>(sxr, xr, ts, c);
    else           score_compute<53,91,1>(sxr, xr, ts, c);
    __syncthreads();
    reduce_rows(ts, redS, c, NP - 53, 53);
    __syncthreads();

    float* scb = g_sc + (size_t)b * HW * 32;
    if (mode == 0) {
        for (int e = c; e < 196; e += 192) {
            int a = e / 14, k = e % 14;
            int j = a - k; if (j < 0) j += 14;
            int lo = min(a, j), hi = max(a, j);
            int id = lo*14 - (lo*(lo-1))/2 + (hi - lo);
            int n = (r + 4*a)*Ww + x;
            scb[n*32 + k] = redS[id];
        }
    } else {
        for (int e = c; e < 182; e += 192) {
            int a = e / 13, m = e % 13 + 1;
            int j = a - m; if (j < 0) j += 14;
            int lo = min(a, j), hi = max(a, j);
            int id = lo*13 - (lo*(lo-1))/2 + (hi - lo - 1);
            int n = x*Ww + r + 4*a;
            scb[n*32 + 13 + m] = redS[id];
        }
    }
}

// ---------------------------------------------------------------------------
// Kernel 3: ring weighted-sum (unchanged)
// ---------------------------------------------------------------------------
__global__ __launch_bounds__(192) void sum_k()
{
    __shared__ float wgt[14*14];
    const int x = blockIdx.x, r = blockIdx.y;
    const int b = blockIdx.z >> 1, mode = blockIdx.z & 1;
    const int c = threadIdx.x;
    const float* base = g_xt + (size_t)b * HW * Cch;
    float* attb = (mode ? g_attw : g_att) + (size_t)b * HW * Cch;
    const float* scb = g_sc + (size_t)b * HW * 32;

    if (c < 14) {
        int n = mode ? (x*Ww + r + 4*c) : ((r + 4*c)*Ww + x);
        const float* srow = scb + n*32;
        float s[27], mx = -1e30f;
#pragma unroll
        for (int k = 0; k < 27; k++) { s[k] = srow[k]; mx = fmaxf(mx, s[k]); }
        float tot = 0.f;
#pragma unroll
        for (int k = 0; k < 27; k++) { s[k] = __expf(s[k] - mx); tot += s[k]; }
        float inv = __fdividef(1.f, tot);
        if (mode == 0) {
#pragma unroll
            for (int k = 0; k < 14; k++) wgt[c*14 + k] = s[k] * inv;
        } else {
#pragma unroll
            for (int m = 1; m < 14; m++) wgt[c*14 + m-1] = s[13 + m] * inv;
        }
    }
    __syncthreads();

    float xr[14];
#pragma unroll
    for (int a = 0; a < 14; a++) {
        int n = mode ? (x*Ww + r + 4*a) : ((r + 4*a)*Ww + x);
        xr[a] = base[n*Cch + c];
    }
#pragma unroll
    for (int a = 0; a < 14; a++) {
        int n = mode ? (x*Ww + r + 4*a) : ((r + 4*a)*Ww + x);
        float o = 0.f;
        if (mode == 0) {
#pragma unroll
            for (int k = 0; k < 14; k++) {
                int j = (a - k + 14) % 14;
                o = fmaf(wgt[a*14 + k], xr[j], o);
            }
        } else {
#pragma unroll
            for (int m = 1; m < 14; m++) {
                int j = (a - m + 14) % 14;
                o = fmaf(wgt[a*14 + m-1], xr[j], o);
            }
        }
        attb[n*Cch + c] = o;
    }
}

// ---------------------------------------------------------------------------
// Kernel 4: FFMA2 GEMM (R7 design) retuned for 4 warps/SMSP.
// Block 128n x 64o, 256 thr, 32 accs/thread (8o x 4n), grid 98x3 = 294
// = 148 SMs x 2 blocks. smem 25.6KB/block, <=128 regs (launch_bounds(256,2)).
// Per warp-k: 2 LDS.128 (A) + 4 conflict-free LDS.32+dup (B) + 16 FFMA2.
// ---------------------------------------------------------------------------
#define GBK 32
#define WSTR 68
#define KSTR 33

#define FFMA2(d, a, b) asm("fma.rn.f32x2 %0, %1, %2, %0;" : "+l"(d) : "l"(a), "l"(b))
#define LDSDUP(bb, addr)                                                      \
    asm volatile("{\n\t.reg .f32 t;\n\tld.shared.f32 t, [%1];\n\t"            \
                 "mov.b64 %0, {t, t};\n\t}" : "=l"(bb) : "r"(addr))

__global__ __launch_bounds__(256, 2) void gemm_k(
    const float* __restrict__ cw,
    const float* __restrict__ bias,
    const float* __restrict__ gamma,
    const float* __restrict__ beta,
    const float* __restrict__ mean,
    const float* __restrict__ var,
    float* __restrict__ out)
{
    __shared__ __align__(16) float wS[GBK * WSTR];    // [k][o]  8.7KB
    __shared__ __align__(16) float catS[128 * KSTR];  // [n][k]  16.9KB
    const int t = threadIdx.x, lane = t & 31, wrp = t >> 5;
    const int ow = wrp & 1, nw = wrp >> 1;   // 2 o-warps x 4 n-warps
    const int ti = lane & 3, tj = lane >> 2; // 4 o-groups x 8 n-groups
    const int r0 = blockIdx.x * 128;         // global row (batch folded)
    const int o0 = blockIdx.y * 64;

    unsigned long long acc[4][4];            // [o-pair][n]
#pragma unroll
    for (int p = 0; p < 4; p++)
#pragma unroll
        for (int nn = 0; nn < 4; nn++) acc[p][nn] = 0ULL;

    // loader coords
    const int kq = t & 7, rowb = t >> 3;     // k-quad, row group

    // B read addresses (4 n per thread)
    unsigned cb0 = (unsigned)__cvta_generic_to_shared(catS);
    unsigned cadr[4];
#pragma unroll
    for (int i = 0; i < 4; i++)
        cadr[i] = cb0 + (unsigned)((nw*32 + tj*4 + i) * KSTR * 4);

    float4 cv[4], wv[2];
#define LOAD_TILE(KC) do {                                                    \
        if ((KC) < Cch) {                                                     \
            _Pragma("unroll")                                                 \
            for (int s = 0; s < 4; s++)                                       \
                cv[s] = *reinterpret_cast<const float4*>(                     \
                    &g_xt[(size_t)(r0 + rowb + 32*s)*Cch + (KC) + kq*4]);     \
        } else {                                                              \
            _Pragma("unroll")                                                 \
            for (int s = 0; s < 4; s++) {                                     \
                size_t ix = (size_t)(r0 + rowb + 32*s)*Cch + (KC) - Cch + kq*4;\
                float4 h = *reinterpret_cast<const float4*>(&g_att[ix]);      \
                float4 w = *reinterpret_cast<const float4*>(&g_attw[ix]);     \
                cv[s] = make_float4(h.x+w.x, h.y+w.y, h.z+w.z, h.w+w.w);      \
            }                                                                 \
        }                                                                     \
        _Pragma("unroll")                                                     \
        for (int s = 0; s < 2; s++)                                           \
            wv[s] = *reinterpret_cast<const float4*>(                         \
                &cw[(o0 + rowb + 32*s)*384 + (KC) + kq*4]);                   \
    } while (0)

    LOAD_TILE(0);
#pragma unroll 1
    for (int it = 0; it < 12; it++) {
        __syncthreads();
        // catS[n][k] transposing store: bank = n + 4kq + j (all distinct)
#pragma unroll
        for (int s = 0; s < 4; s++) {
            const float* cp = &cv[s].x;
#pragma unroll
            for (int j = 0; j < 4; j++)
                catS[(rowb + 32*s)*KSTR + kq*4 + j] = cp[j];
        }
#pragma unroll
        for (int s = 0; s < 2; s++) {
            const float* wp = &wv[s].x;
#pragma unroll
            for (int j = 0; j < 4; j++)
                wS[(kq*4 + j)*WSTR + rowb + 32*s] = wp[j];
        }
        __syncthreads();
        if (it < 11) LOAD_TILE((it + 1) * GBK);
#pragma unroll 16
        for (int k = 0; k < GBK; k++) {
            ulonglong2 A0 = *reinterpret_cast<const ulonglong2*>(
                                &wS[k*WSTR + ow*32 + ti*8]);
            ulonglong2 A1 = *reinterpret_cast<const ulonglong2*>(
                                &wS[k*WSTR + ow*32 + ti*8 + 4]);
            unsigned long long a[4] = {A0.x, A0.y, A1.x, A1.y};
            unsigned long long bb[4];
#pragma unroll
            for (int i = 0; i < 4; i++)
                LDSDUP(bb[i], cadr[i] + (unsigned)(4*k));
#pragma unroll
            for (int p = 0; p < 4; p++)
#pragma unroll
                for (int nn = 0; nn < 4; nn++)
                    FFMA2(acc[p][nn], a[p], bb[nn]);
        }
    }

    // epilogue: bias + BN(eval) + exact GELU; 4 consecutive n -> STG.128
    const int rr = r0 + nw*32 + tj*4;
    const int bq = rr / HW;                  // quad never splits batch
    const int nq = rr - bq*HW;
#pragma unroll
    for (int p = 0; p < 4; p++) {
#pragma unroll
        for (int q = 0; q < 2; q++) {
            const int o = o0 + ow*32 + ti*8 + 2*p + q;
            const float bi  = bias[o];
            const float inv = gamma[o] * rsqrtf(var[o] + 1e-5f);
            const float mu  = mean[o], bt = beta[o];
            float4 rv; float* rp = &rv.x;
#pragma unroll
            for (int nn = 0; nn < 4; nn++) {
                unsigned long long v = acc[p][nn];
                float yv = q ? __uint_as_float((unsigned)(v >> 32))
                             : __uint_as_float((unsigned)v);
                float y = (yv + bi - mu) * inv + bt;
                rp[nn] = 0.5f * y * (1.0f + erff(y * 0.70710678118654752f));
            }
            *reinterpret_cast<float4*>(
                &out[(size_t)(bq*Cch + o)*HW + nq]) = rv;
        }
    }
}

// ---------------------------------------------------------------------------
extern "C" void kernel_launch(void* const* d_in, const int* in_sizes, int n_in,
                              void* d_out, int out_size)
{
    const float* x     = (const float*)d_in[0];
    const float* cw    = (const float*)d_in[1];
    const float* cb    = (const float*)d_in[2];
    const float* gamma = (const float*)d_in[3];
    const float* beta  = (const float*)d_in[4];
    const float* mean  = (const float*)d_in[5];
    const float* var   = (const float*)d_in[6];
    float* out = (float*)d_out;

    transpose_k<<<dim3(HW/32, Cch/32, Bsz), dim3(32, 8)>>>(x);
    score_k<<<dim3(56, 4, 2*Bsz), 192>>>();
    sum_k<<<dim3(56, 4, 2*Bsz), 192>>>();
    gemm_k<<<dim3(98, 3), 256>>>(cw, cb, gamma, beta, mean, var, out);
}